// round 14
// baseline (speedup 1.0000x reference)
#include <cuda_runtime.h>
#include <cuda_fp16.h>

// MaskedCommonWeightSimpleLinearGNN — 2 kernels:
//  1) build (high-occupancy, ~7 blocks/SM): A scan + LW gather -> ELL + s1.
//     (R13 post-mortem: fused build was occupancy-capped at 4 blocks/SM by the
//      layer code's 64 regs -> only ~3.7 TB/s; standalone runs ~5.3 TB/s.)
//  2) persistent layers kernel (592 = 4/SM): stage ELL from L2 into SMEM once,
//     prep M/c0/c1, layer1 (fp32 x) -> fp16 buf, barrier, layer2 (+s2),
//     barrier, layer3 + fused M/rank-1 epilogue.
//   out = (w^3 x) M + (w^2 1) c0^T + (w 1) c1^T + 1 b2^T

#define NN    8192
#define DD    64
#define CAP   160     // Binomial(8192,0.01): mean 82, sigma 9 -> mean+8.7sigma
#define RPBX  14
#define PRIV  20      // per-lane slots; Binomial(256,0.01) mean 2.56 -> +11sigma
#define GRID  592     // 4 * 148 (layers kernel)
#define NFULL 496     // blocks with 14 rows; rest have 13

// ---- allocation-free scratch ----
__device__ __align__(16) unsigned short g_cols[(size_t)NN * CAP];  // 2.5 MB
__device__ __align__(16) float          g_vals[(size_t)NN * CAP];  // 5 MB
__device__ __align__(16) int            g_cnt[NN];
__device__ __align__(16) float  g_s1[NN];
__device__ __align__(16) float  g_s2[NN];
__device__ __align__(16) float  g_M[DD * DD];
__device__ __align__(16) float  g_c0[DD];
__device__ __align__(16) float  g_c1[DD];
__device__ __align__(16) __half g_buf0[(size_t)NN * DD];
__device__ __align__(16) __half g_buf1[(size_t)NN * DD];
__device__ unsigned g_count = 0;
__device__ unsigned g_gen   = 0;

// generation-based grid barrier (replay-safe)
__device__ __forceinline__ void grid_barrier() {
    __threadfence();
    __syncthreads();
    if (threadIdx.x == 0) {
        unsigned gen = *(volatile unsigned*)&g_gen;
        unsigned t = atomicAdd(&g_count, 1);
        if (t == GRID - 1) {
            g_count = 0;
            __threadfence();
            atomicAdd(&g_gen, 1);
        } else {
            while (*(volatile unsigned*)&g_gen == gen) __nanosleep(64);
        }
    }
    __syncthreads();
    __threadfence();
}

// ============================================================================
// Kernel 1: build (one warp per row, 8 warps/block, 1024 blocks).
// Wide-prefetch A scan (4 float4/lane in flight), per-lane private slot
// compaction (order-free), LW gather, s1.
// ============================================================================
__global__ void __launch_bounds__(256)
build_kernel(const float* __restrict__ A, const float* __restrict__ LW) {
    __shared__ unsigned short sPriv[8][PRIV][32];   // 10 KB
    __shared__ unsigned short sCols[8][CAP];        // 2.5 KB

    int wid  = threadIdx.x >> 5;
    int lane = threadIdx.x & 31;
    int row  = blockIdx.x * 8 + wid;

    const float4* a4 = reinterpret_cast<const float4*>(A + (size_t)row * NN);
    unsigned short (*priv)[32] = sPriv[wid];
    unsigned short* wc = sCols[wid];

    int myc = 0;
    float4 c0 = __ldcs(&a4[lane]);
    float4 c1 = __ldcs(&a4[32 + lane]);
    float4 c2 = __ldcs(&a4[64 + lane]);
    float4 c3 = __ldcs(&a4[96 + lane]);
    #pragma unroll 1
    for (int it = 0; it < NN / 512; ++it) {
        float4 n0, n1, n2, n3;
        if (it + 1 < NN / 512) {
            int nb = (it + 1) * 128;
            n0 = __ldcs(&a4[nb + lane]);
            n1 = __ldcs(&a4[nb + 32 + lane]);
            n2 = __ldcs(&a4[nb + 64 + lane]);
            n3 = __ldcs(&a4[nb + 96 + lane]);
        }
        int b0c = it * 512 + lane * 4;
        if (c0.x != 0.0f) { if (myc < PRIV) priv[myc][lane] = (unsigned short)(b0c    ); ++myc; }
        if (c0.y != 0.0f) { if (myc < PRIV) priv[myc][lane] = (unsigned short)(b0c + 1); ++myc; }
        if (c0.z != 0.0f) { if (myc < PRIV) priv[myc][lane] = (unsigned short)(b0c + 2); ++myc; }
        if (c0.w != 0.0f) { if (myc < PRIV) priv[myc][lane] = (unsigned short)(b0c + 3); ++myc; }
        int b1c = b0c + 128;
        if (c1.x != 0.0f) { if (myc < PRIV) priv[myc][lane] = (unsigned short)(b1c    ); ++myc; }
        if (c1.y != 0.0f) { if (myc < PRIV) priv[myc][lane] = (unsigned short)(b1c + 1); ++myc; }
        if (c1.z != 0.0f) { if (myc < PRIV) priv[myc][lane] = (unsigned short)(b1c + 2); ++myc; }
        if (c1.w != 0.0f) { if (myc < PRIV) priv[myc][lane] = (unsigned short)(b1c + 3); ++myc; }
        int b2c = b0c + 256;
        if (c2.x != 0.0f) { if (myc < PRIV) priv[myc][lane] = (unsigned short)(b2c    ); ++myc; }
        if (c2.y != 0.0f) { if (myc < PRIV) priv[myc][lane] = (unsigned short)(b2c + 1); ++myc; }
        if (c2.z != 0.0f) { if (myc < PRIV) priv[myc][lane] = (unsigned short)(b2c + 2); ++myc; }
        if (c2.w != 0.0f) { if (myc < PRIV) priv[myc][lane] = (unsigned short)(b2c + 3); ++myc; }
        int b3c = b0c + 384;
        if (c3.x != 0.0f) { if (myc < PRIV) priv[myc][lane] = (unsigned short)(b3c    ); ++myc; }
        if (c3.y != 0.0f) { if (myc < PRIV) priv[myc][lane] = (unsigned short)(b3c + 1); ++myc; }
        if (c3.z != 0.0f) { if (myc < PRIV) priv[myc][lane] = (unsigned short)(b3c + 2); ++myc; }
        if (c3.w != 0.0f) { if (myc < PRIV) priv[myc][lane] = (unsigned short)(b3c + 3); ++myc; }
        c0 = n0; c1 = n1; c2 = n2; c3 = n3;
    }
    if (myc > PRIV) myc = PRIV;

    // warp scan + compaction (order-free: fp32 reorder ~1e-7 << tol)
    int inc = myc;
    #pragma unroll
    for (int o = 1; o < 32; o <<= 1) {
        int t = __shfl_up_sync(0xffffffffu, inc, o);
        if (lane >= o) inc += t;
    }
    int base = inc - myc;
    int cnt  = __shfl_sync(0xffffffffu, inc, 31);
    if (cnt > CAP) cnt = CAP;
    for (int j = 0; j < myc; ++j) {
        int p = base + j;
        if (p < CAP) wc[p] = priv[j][lane];
    }
    __syncwarp();

    // gather LW, coalesced writeout, row sum
    const float* lw = LW + (size_t)row * NN;
    unsigned short* gcols = g_cols + (size_t)row * CAP;
    float*          gvals = g_vals + (size_t)row * CAP;

    float s = 0.0f;
    #pragma unroll
    for (int j = 0; j < CAP / 32; ++j) {
        int k = j * 32 + lane;
        if (k < cnt) {
            unsigned short c = wc[k];
            float v = __ldcs(&lw[c]);
            gvals[k] = v;
            gcols[k] = c;
            s += v;
        }
    }
    #pragma unroll
    for (int o = 16; o; o >>= 1) s += __shfl_xor_sync(0xffffffffu, s, o);
    if (lane == 0) {
        g_cnt[row] = cnt;
        g_s1[row]  = s;
    }
}

// ============================================================================
// SpMM row helpers (SMEM ELL, global gathers, fp32 accumulation)
// ============================================================================
__device__ __forceinline__ float4 spmm_row_f32(const float4* __restrict__ x4,
                                               const unsigned short* cr,
                                               const float* vr, int cnt, int l) {
    float4 a0 = make_float4(0.f,0.f,0.f,0.f), a1 = a0, a2 = a0, a3 = a0;
    int k = 0;
    for (; k + 8 <= cnt; k += 8) {
        int   c0 = cr[k],   c1 = cr[k+1], c2 = cr[k+2], c3 = cr[k+3];
        int   c4 = cr[k+4], c5 = cr[k+5], c6 = cr[k+6], c7 = cr[k+7];
        float v0 = vr[k],   v1 = vr[k+1], v2 = vr[k+2], v3 = vr[k+3];
        float v4 = vr[k+4], v5 = vr[k+5], v6 = vr[k+6], v7 = vr[k+7];
        float4 g0 = __ldg(&x4[c0 * 16 + l]);
        float4 g1 = __ldg(&x4[c1 * 16 + l]);
        float4 g2 = __ldg(&x4[c2 * 16 + l]);
        float4 g3 = __ldg(&x4[c3 * 16 + l]);
        float4 g4 = __ldg(&x4[c4 * 16 + l]);
        float4 g5 = __ldg(&x4[c5 * 16 + l]);
        float4 g6 = __ldg(&x4[c6 * 16 + l]);
        float4 g7 = __ldg(&x4[c7 * 16 + l]);
        a0.x += v0*g0.x; a0.y += v0*g0.y; a0.z += v0*g0.z; a0.w += v0*g0.w;
        a1.x += v1*g1.x; a1.y += v1*g1.y; a1.z += v1*g1.z; a1.w += v1*g1.w;
        a2.x += v2*g2.x; a2.y += v2*g2.y; a2.z += v2*g2.z; a2.w += v2*g2.w;
        a3.x += v3*g3.x; a3.y += v3*g3.y; a3.z += v3*g3.z; a3.w += v3*g3.w;
        a0.x += v4*g4.x; a0.y += v4*g4.y; a0.z += v4*g4.z; a0.w += v4*g4.w;
        a1.x += v5*g5.x; a1.y += v5*g5.y; a1.z += v5*g5.z; a1.w += v5*g5.w;
        a2.x += v6*g6.x; a2.y += v6*g6.y; a2.z += v6*g6.z; a2.w += v6*g6.w;
        a3.x += v7*g7.x; a3.y += v7*g7.y; a3.z += v7*g7.z; a3.w += v7*g7.w;
    }
    for (; k < cnt; ++k) {
        int c = cr[k]; float v = vr[k];
        float4 g = __ldg(&x4[c * 16 + l]);
        a0.x += v*g.x; a0.y += v*g.y; a0.z += v*g.z; a0.w += v*g.w;
    }
    float4 y;
    y.x = (a0.x + a1.x) + (a2.x + a3.x);
    y.y = (a0.y + a1.y) + (a2.y + a3.y);
    y.z = (a0.z + a1.z) + (a2.z + a3.z);
    y.w = (a0.w + a1.w) + (a2.w + a3.w);
    return y;
}

__device__ __forceinline__ float4 spmm_row_f16(const uint2* __restrict__ xh,
                                               const unsigned short* cr,
                                               const float* vr, int cnt, int l) {
    float4 a0 = make_float4(0.f,0.f,0.f,0.f), a1 = a0, a2 = a0, a3 = a0;
    int k = 0;
    for (; k + 8 <= cnt; k += 8) {
        int   c0 = cr[k],   c1 = cr[k+1], c2 = cr[k+2], c3 = cr[k+3];
        int   c4 = cr[k+4], c5 = cr[k+5], c6 = cr[k+6], c7 = cr[k+7];
        float v0 = vr[k],   v1 = vr[k+1], v2 = vr[k+2], v3 = vr[k+3];
        float v4 = vr[k+4], v5 = vr[k+5], v6 = vr[k+6], v7 = vr[k+7];
        uint2 g0 = __ldg(&xh[c0 * 16 + l]);
        uint2 g1 = __ldg(&xh[c1 * 16 + l]);
        uint2 g2 = __ldg(&xh[c2 * 16 + l]);
        uint2 g3 = __ldg(&xh[c3 * 16 + l]);
        uint2 g4 = __ldg(&xh[c4 * 16 + l]);
        uint2 g5 = __ldg(&xh[c5 * 16 + l]);
        uint2 g6 = __ldg(&xh[c6 * 16 + l]);
        uint2 g7 = __ldg(&xh[c7 * 16 + l]);
        #define ACC_H(ar, gg, vv) { \
            float2 f0 = __half22float2(*(const __half2*)&(gg).x); \
            float2 f1 = __half22float2(*(const __half2*)&(gg).y); \
            (ar).x += (vv) * f0.x; (ar).y += (vv) * f0.y; \
            (ar).z += (vv) * f1.x; (ar).w += (vv) * f1.y; }
        ACC_H(a0, g0, v0) ACC_H(a1, g1, v1) ACC_H(a2, g2, v2) ACC_H(a3, g3, v3)
        ACC_H(a0, g4, v4) ACC_H(a1, g5, v5) ACC_H(a2, g6, v6) ACC_H(a3, g7, v7)
    }
    for (; k < cnt; ++k) {
        int c = cr[k]; float v = vr[k];
        uint2 g = __ldg(&xh[c * 16 + l]);
        ACC_H(a0, g, v)
        #undef ACC_H
    }
    float4 y;
    y.x = (a0.x + a1.x) + (a2.x + a3.x);
    y.y = (a0.y + a1.y) + (a2.y + a3.y);
    y.z = (a0.z + a1.z) + (a2.z + a3.z);
    y.w = (a0.w + a1.w) + (a2.w + a3.w);
    return y;
}

__device__ __forceinline__ uint2 pack_half4(float4 y) {
    __half2 h0 = __floats2half2_rn(y.x, y.y);
    __half2 h1 = __floats2half2_rn(y.z, y.w);
    uint2 u;
    u.x = *(unsigned*)&h0;
    u.y = *(unsigned*)&h1;
    return u;
}

// ============================================================================
// Kernel 2: persistent layers kernel (592 blocks, 4/SM).
// ============================================================================
__global__ void __launch_bounds__(256, 4)
layers_kernel(const float* __restrict__ x,
              const float* __restrict__ W0, const float* __restrict__ b0,
              const float* __restrict__ W1, const float* __restrict__ b1,
              const float* __restrict__ W2, const float* __restrict__ b2,
              float* __restrict__ out) {
    __shared__ __align__(16) unsigned short sC[RPBX * CAP];   // 4.4 KB
    __shared__ __align__(16) float          sV[RPBX * CAP];   // 8.75 KB
    __shared__ __align__(16) int            sCnt[16];
    __shared__ __align__(16) float          shY[RPBX][DD];    // 3.5 KB
    __shared__ __align__(16) char uBuf[DD * DD * 4];          // 16 KB union

    int tid = threadIdx.x;
    int bid = blockIdx.x;

    int row0  = (bid < NFULL) ? bid * 14 : NFULL * 14 + (bid - NFULL) * 13;
    int nrows = (bid < NFULL) ? 14 : 13;

    // ---- stage this block's ELL from global (L2-hot: just written) ---------
    if (tid < nrows) sCnt[tid] = g_cnt[row0 + tid];
    {
        const uint2* gc2 = reinterpret_cast<const uint2*>(g_cols + (size_t)row0 * CAP);
        uint2* sC2 = reinterpret_cast<uint2*>(sC);
        int n4 = nrows * CAP / 4;
        for (int i = tid; i < n4; i += 256) sC2[i] = gc2[i];
        const float4* gv4 = reinterpret_cast<const float4*>(g_vals + (size_t)row0 * CAP);
        float4* sV4 = reinterpret_cast<float4*>(sV);
        for (int i = tid; i < n4; i += 256) sV4[i] = gv4[i];
    }

    // ---- prep on blocks 0..64 (uBuf scratch; before first barrier) ---------
    if (bid < 64) {
        __syncthreads();                    // sC/sV staged (uBuf independent)
        float* scr = (float*)uBuf;
        int d = bid;
        int e = tid & 63, q = tid >> 6;
        float p = 0.0f;
        #pragma unroll
        for (int j = 0; j < 16; ++j) {
            int f = q * 16 + j;
            p += __ldg(&W0[f * DD + d]) * __ldg(&W1[e * DD + f]);
        }
        scr[q * DD + e] = p;
        __syncthreads();
        float pe = 0.0f;
        if (tid < DD) pe = scr[tid] + scr[DD + tid] + scr[2 * DD + tid] + scr[3 * DD + tid];
        __syncthreads();
        if (tid < DD) scr[tid] = pe;
        __syncthreads();
        float m = 0.0f;
        #pragma unroll
        for (int j = 0; j < 16; ++j) {
            int ee = q * 16 + j;
            m += scr[ee] * __ldg(&W2[e * DD + ee]);
        }
        scr[DD + q * DD + e] = m;
        __syncthreads();
        if (tid < DD)
            g_M[d * DD + tid] = scr[DD + tid] + scr[2 * DD + tid] +
                                scr[3 * DD + tid] + scr[4 * DD + tid];
    } else if (bid == 64) {
        __syncthreads();
        float* scr = (float*)uBuf;
        int t = tid & 63, q = tid >> 6;
        float s = 0.0f, s1p = 0.0f;
        #pragma unroll
        for (int j = 0; j < 16; ++j) {
            int f = q * 16 + j;
            s   += __ldg(&W1[t * DD + f]) * __ldg(&b0[f]);
            s1p += __ldg(&W2[t * DD + f]) * __ldg(&b1[f]);
        }
        scr[q * DD + t]       = s;
        scr[256 + q * DD + t] = s1p;
        __syncthreads();
        if (tid < DD) {
            g_c1[tid] = scr[256 + tid] + scr[320 + tid] + scr[384 + tid] + scr[448 + tid];
            scr[512 + tid] = scr[tid] + scr[64 + tid] + scr[128 + tid] + scr[192 + tid];
        }
        __syncthreads();
        float c0p = 0.0f;
        #pragma unroll
        for (int j = 0; j < 16; ++j) {
            int ee = q * 16 + j;
            c0p += __ldg(&W2[t * DD + ee]) * scr[512 + ee];
        }
        __syncthreads();
        scr[q * DD + t] = c0p;
        __syncthreads();
        if (tid < DD) g_c0[tid] = scr[tid] + scr[64 + tid] + scr[128 + tid] + scr[192 + tid];
    } else {
        __syncthreads();                    // match staging sync
    }

    // ---- layer 1: y1 = w x (fp32 gathers, fp16 store) ----------------------
    int r = tid >> 4, l = tid & 15;
    bool active = (r < nrows);
    int row = row0 + (active ? r : 0);
    int cnt = active ? sCnt[r] : 0;
    const unsigned short* cr = sC + (active ? r : 0) * CAP;
    const float*          vr = sV + (active ? r : 0) * CAP;

    float4 y = spmm_row_f32(reinterpret_cast<const float4*>(x), cr, vr, cnt, l);
    if (active)
        reinterpret_cast<uint2*>(g_buf0)[(size_t)row * 16 + l] = pack_half4(y);

    grid_barrier();   // buf0 + M/c0/c1 complete chip-wide

    // stage M into uBuf (prep scratch dead)
    {
        float4* sM4 = reinterpret_cast<float4*>(uBuf);
        const float4* gm4 = reinterpret_cast<const float4*>(g_M);
        #pragma unroll
        for (int j = 0; j < 4; ++j) sM4[j * 256 + tid] = gm4[j * 256 + tid];
    }

    // ---- layer 2: y2 = w y1 (fp16 gathers), s2 = w s1 -----------------------
    y = spmm_row_f16(reinterpret_cast<const uint2*>(g_buf0), cr, vr, cnt, l);
    if (active)
        reinterpret_cast<uint2*>(g_buf1)[(size_t)row * 16 + l] = pack_half4(y);

    {
        float s2a = 0.0f;
        for (int kk = l; kk < cnt; kk += 16)
            s2a += vr[kk] * __ldg(&g_s1[cr[kk]]);
        #pragma unroll
        for (int o = 8; o; o >>= 1) s2a += __shfl_xor_sync(0xffffffffu, s2a, o);
        if (active && l == 0) g_s2[row] = s2a;
    }

    grid_barrier();   // buf1 + s2 complete chip-wide

    // ---- layer 3: out = (w y2) M + s2 c0^T + s1 c1^T + b2 -------------------
    y = spmm_row_f16(reinterpret_cast<const uint2*>(g_buf1), cr, vr, cnt, l);
    if (active)
        reinterpret_cast<float4*>(&shY[r][0])[l] = y;
    __syncthreads();

    if (active) {
        const float* sM = (const float*)uBuf;
        float s1v = g_s1[row], s2v = g_s2[row];
        float4 c0v = __ldg(&reinterpret_cast<const float4*>(g_c0)[l]);
        float4 c1v = __ldg(&reinterpret_cast<const float4*>(g_c1)[l]);
        float4 bv  = __ldg(&reinterpret_cast<const float4*>(b2)[l]);

        float4 acc;
        acc.x = s2v * c0v.x + s1v * c1v.x + bv.x;
        acc.y = s2v * c0v.y + s1v * c1v.y + bv.y;
        acc.z = s2v * c0v.z + s1v * c1v.z + bv.z;
        acc.w = s2v * c0v.w + s1v * c1v.w + bv.w;

        #pragma unroll 8
        for (int d = 0; d < DD; ++d) {
            float yd  = shY[r][d];
            float4 m4 = reinterpret_cast<const float4*>(sM + d * DD)[l];
            acc.x += yd * m4.x; acc.y += yd * m4.y;
            acc.z += yd * m4.z; acc.w += yd * m4.w;
        }
        reinterpret_cast<float4*>(out)[(size_t)row * 16 + l] = acc;
    }
}

// ============================================================================
// Launch (2 kernels)
// ============================================================================
extern "C" void kernel_launch(void* const* d_in, const int* in_sizes, int n_in,
                              void* d_out, int out_size) {
    const float* x  = (const float*)d_in[0];
    const float* A  = (const float*)d_in[1];
    const float* LW = (const float*)d_in[2];
    const float* W0 = (const float*)d_in[3];
    const float* b0 = (const float*)d_in[4];
    const float* W1 = (const float*)d_in[5];
    const float* b1 = (const float*)d_in[6];
    const float* W2 = (const float*)d_in[7];
    const float* b2 = (const float*)d_in[8];

    build_kernel <<<NN / 8, 256>>>(A, LW);
    layers_kernel<<<GRID, 256>>>(x, W0, b0, W1, b1, W2, b2, (float*)d_out);
}

// round 15
// speedup vs baseline: 1.0868x; 1.0868x over previous
#include <cuda_runtime.h>
#include <cuda_fp16.h>

// MaskedCommonWeightSimpleLinearGNN — single persistent kernel (R13 base),
// fp16 intermediates, software-pipelined gather loops in layers 2/3
// (depth-2 groups of 4: next group's loads issue before current group's
// FMAs consume -> latency overlapped instead of serialized per group).
//   out = (w^3 x) M + (w^2 1) c0^T + (w 1) c1^T + 1 b2^T
// 592 blocks = 4/SM exactly. Blocks 0..495 own 14 rows, rest 13.

#define NN    8192
#define DD    64
#define CAP   160     // Binomial(8192,0.01): mean 82, sigma 9 -> mean+8.7sigma
#define RPBX  14
#define PRIV  20      // per-lane slots; Binomial(256,0.01) mean 2.56 -> +11sigma
#define GRID  592     // 4 * 148
#define NFULL 496     // blocks with 14 rows; rest have 13

// ---- allocation-free scratch ----
__device__ __align__(16) float  g_s1[NN];
__device__ __align__(16) float  g_s2[NN];
__device__ __align__(16) float  g_M[DD * DD];
__device__ __align__(16) float  g_c0[DD];
__device__ __align__(16) float  g_c1[DD];
__device__ __align__(16) __half g_buf0[(size_t)NN * DD];   // 1 MB
__device__ __align__(16) __half g_buf1[(size_t)NN * DD];   // 1 MB
__device__ unsigned g_count = 0;
__device__ unsigned g_gen   = 0;

// generation-based grid barrier (replay-safe)
__device__ __forceinline__ void grid_barrier() {
    __threadfence();
    __syncthreads();
    if (threadIdx.x == 0) {
        unsigned gen = *(volatile unsigned*)&g_gen;
        unsigned t = atomicAdd(&g_count, 1);
        if (t == GRID - 1) {
            g_count = 0;
            __threadfence();
            atomicAdd(&g_gen, 1);
        } else {
            while (*(volatile unsigned*)&g_gen == gen) __nanosleep(64);
        }
    }
    __syncthreads();
    __threadfence();
}

// fp32 gather SpMM, unroll-8 (layer 1; x input fp32)
__device__ __forceinline__ float4 spmm_row_f32(const float4* __restrict__ x4,
                                               const unsigned short* cr,
                                               const float* vr, int cnt, int l) {
    float4 a0 = make_float4(0.f,0.f,0.f,0.f), a1 = a0, a2 = a0, a3 = a0;
    int k = 0;
    for (; k + 8 <= cnt; k += 8) {
        int   c0 = cr[k],   c1 = cr[k+1], c2 = cr[k+2], c3 = cr[k+3];
        int   c4 = cr[k+4], c5 = cr[k+5], c6 = cr[k+6], c7 = cr[k+7];
        float v0 = vr[k],   v1 = vr[k+1], v2 = vr[k+2], v3 = vr[k+3];
        float v4 = vr[k+4], v5 = vr[k+5], v6 = vr[k+6], v7 = vr[k+7];
        float4 g0 = __ldg(&x4[c0 * 16 + l]);
        float4 g1 = __ldg(&x4[c1 * 16 + l]);
        float4 g2 = __ldg(&x4[c2 * 16 + l]);
        float4 g3 = __ldg(&x4[c3 * 16 + l]);
        float4 g4 = __ldg(&x4[c4 * 16 + l]);
        float4 g5 = __ldg(&x4[c5 * 16 + l]);
        float4 g6 = __ldg(&x4[c6 * 16 + l]);
        float4 g7 = __ldg(&x4[c7 * 16 + l]);
        a0.x += v0*g0.x; a0.y += v0*g0.y; a0.z += v0*g0.z; a0.w += v0*g0.w;
        a1.x += v1*g1.x; a1.y += v1*g1.y; a1.z += v1*g1.z; a1.w += v1*g1.w;
        a2.x += v2*g2.x; a2.y += v2*g2.y; a2.z += v2*g2.z; a2.w += v2*g2.w;
        a3.x += v3*g3.x; a3.y += v3*g3.y; a3.z += v3*g3.z; a3.w += v3*g3.w;
        a0.x += v4*g4.x; a0.y += v4*g4.y; a0.z += v4*g4.z; a0.w += v4*g4.w;
        a1.x += v5*g5.x; a1.y += v5*g5.y; a1.z += v5*g5.z; a1.w += v5*g5.w;
        a2.x += v6*g6.x; a2.y += v6*g6.y; a2.z += v6*g6.z; a2.w += v6*g6.w;
        a3.x += v7*g7.x; a3.y += v7*g7.y; a3.z += v7*g7.z; a3.w += v7*g7.w;
    }
    for (; k < cnt; ++k) {
        int c = cr[k]; float v = vr[k];
        float4 g = __ldg(&x4[c * 16 + l]);
        a0.x += v*g.x; a0.y += v*g.y; a0.z += v*g.z; a0.w += v*g.w;
    }
    float4 y;
    y.x = (a0.x + a1.x) + (a2.x + a3.x);
    y.y = (a0.y + a1.y) + (a2.y + a3.y);
    y.z = (a0.z + a1.z) + (a2.z + a3.z);
    y.w = (a0.w + a1.w) + (a2.w + a3.w);
    return y;
}

#define ACC_H(ar, gg, vv) { \
    float2 f0_ = __half22float2(*(const __half2*)&(gg).x); \
    float2 f1_ = __half22float2(*(const __half2*)&(gg).y); \
    (ar).x += (vv) * f0_.x; (ar).y += (vv) * f0_.y; \
    (ar).z += (vv) * f1_.x; (ar).w += (vv) * f1_.y; }

// fp16 gather SpMM, depth-2 software pipeline (groups of 4; 8 loads in flight,
// accumulation of group i overlaps latency of group i+1)
__device__ __forceinline__ float4 spmm_row_f16(const uint2* __restrict__ xh,
                                               const unsigned short* cr,
                                               const float* vr, int cnt, int l) {
    float4 a0 = make_float4(0.f,0.f,0.f,0.f), a1 = a0, a2 = a0, a3 = a0;
    int kmain = cnt & ~3;
    int k = 0;
    if (kmain >= 4) {
        uint2 g0 = __ldg(&xh[cr[0] * 16 + l]);
        uint2 g1 = __ldg(&xh[cr[1] * 16 + l]);
        uint2 g2 = __ldg(&xh[cr[2] * 16 + l]);
        uint2 g3 = __ldg(&xh[cr[3] * 16 + l]);
        for (k = 4; k < kmain; k += 4) {
            uint2 h0 = __ldg(&xh[cr[k    ] * 16 + l]);
            uint2 h1 = __ldg(&xh[cr[k + 1] * 16 + l]);
            uint2 h2 = __ldg(&xh[cr[k + 2] * 16 + l]);
            uint2 h3 = __ldg(&xh[cr[k + 3] * 16 + l]);
            float v0 = vr[k-4], v1 = vr[k-3], v2 = vr[k-2], v3 = vr[k-1];
            ACC_H(a0, g0, v0) ACC_H(a1, g1, v1) ACC_H(a2, g2, v2) ACC_H(a3, g3, v3)
            g0 = h0; g1 = h1; g2 = h2; g3 = h3;
        }
        float v0 = vr[kmain-4], v1 = vr[kmain-3], v2 = vr[kmain-2], v3 = vr[kmain-1];
        ACC_H(a0, g0, v0) ACC_H(a1, g1, v1) ACC_H(a2, g2, v2) ACC_H(a3, g3, v3)
    }
    for (k = kmain; k < cnt; ++k) {
        uint2 g = __ldg(&xh[cr[k] * 16 + l]);
        float v = vr[k];
        ACC_H(a0, g, v)
    }
    float4 y;
    y.x = (a0.x + a1.x) + (a2.x + a3.x);
    y.y = (a0.y + a1.y) + (a2.y + a3.y);
    y.z = (a0.z + a1.z) + (a2.z + a3.z);
    y.w = (a0.w + a1.w) + (a2.w + a3.w);
    return y;
}

__device__ __forceinline__ uint2 pack_half4(float4 y) {
    __half2 h0 = __floats2half2_rn(y.x, y.y);
    __half2 h1 = __floats2half2_rn(y.z, y.w);
    uint2 u;
    u.x = *(unsigned*)&h0;
    u.y = *(unsigned*)&h1;
    return u;
}

__global__ void __launch_bounds__(256, 4)
mega_kernel(const float* __restrict__ A,  const float* __restrict__ LW,
            const float* __restrict__ x,
            const float* __restrict__ W0, const float* __restrict__ b0,
            const float* __restrict__ W1, const float* __restrict__ b1,
            const float* __restrict__ W2, const float* __restrict__ b2,
            float* __restrict__ out) {
    __shared__ __align__(16) unsigned short sC[RPBX * CAP];   // 4.4 KB
    __shared__ __align__(16) float          sV[RPBX * CAP];   // 8.75 KB
    __shared__ __align__(16) int            sCnt[16];
    __shared__ __align__(16) float          shY[RPBX][DD];    // 3.5 KB
    __shared__ __align__(16) char uBuf[DD * DD * 4];          // 16 KB union

    int tid  = threadIdx.x;
    int wid  = tid >> 5;
    int lane = tid & 31;
    int bid  = blockIdx.x;

    int row0  = (bid < NFULL) ? bid * 14 : NFULL * 14 + (bid - NFULL) * 13;
    int nrows = (bid < NFULL) ? 14 : 13;

    // ---------------- phase 1: build nrows rows into SMEM -------------------
    {
        unsigned short (*priv)[32] =
            (unsigned short (*)[32])((unsigned short*)uBuf + wid * PRIV * 32);

        for (int lr = wid; lr < nrows; lr += 8) {
            int row = row0 + lr;
            const float4* a4 = reinterpret_cast<const float4*>(A + (size_t)row * NN);

            int myc = 0;
            float4 c0 = __ldcs(&a4[lane]);
            float4 c1 = __ldcs(&a4[32 + lane]);
            float4 c2 = __ldcs(&a4[64 + lane]);
            float4 c3 = __ldcs(&a4[96 + lane]);
            #pragma unroll 1
            for (int it = 0; it < NN / 512; ++it) {
                float4 n0, n1, n2, n3;
                if (it + 1 < NN / 512) {
                    int nb = (it + 1) * 128;
                    n0 = __ldcs(&a4[nb + lane]);
                    n1 = __ldcs(&a4[nb + 32 + lane]);
                    n2 = __ldcs(&a4[nb + 64 + lane]);
                    n3 = __ldcs(&a4[nb + 96 + lane]);
                }
                int b0c = it * 512 + lane * 4;
                if (c0.x != 0.0f) { if (myc < PRIV) priv[myc][lane] = (unsigned short)(b0c    ); ++myc; }
                if (c0.y != 0.0f) { if (myc < PRIV) priv[myc][lane] = (unsigned short)(b0c + 1); ++myc; }
                if (c0.z != 0.0f) { if (myc < PRIV) priv[myc][lane] = (unsigned short)(b0c + 2); ++myc; }
                if (c0.w != 0.0f) { if (myc < PRIV) priv[myc][lane] = (unsigned short)(b0c + 3); ++myc; }
                int b1c = b0c + 128;
                if (c1.x != 0.0f) { if (myc < PRIV) priv[myc][lane] = (unsigned short)(b1c    ); ++myc; }
                if (c1.y != 0.0f) { if (myc < PRIV) priv[myc][lane] = (unsigned short)(b1c + 1); ++myc; }
                if (c1.z != 0.0f) { if (myc < PRIV) priv[myc][lane] = (unsigned short)(b1c + 2); ++myc; }
                if (c1.w != 0.0f) { if (myc < PRIV) priv[myc][lane] = (unsigned short)(b1c + 3); ++myc; }
                int b2c = b0c + 256;
                if (c2.x != 0.0f) { if (myc < PRIV) priv[myc][lane] = (unsigned short)(b2c    ); ++myc; }
                if (c2.y != 0.0f) { if (myc < PRIV) priv[myc][lane] = (unsigned short)(b2c + 1); ++myc; }
                if (c2.z != 0.0f) { if (myc < PRIV) priv[myc][lane] = (unsigned short)(b2c + 2); ++myc; }
                if (c2.w != 0.0f) { if (myc < PRIV) priv[myc][lane] = (unsigned short)(b2c + 3); ++myc; }
                int b3c = b0c + 384;
                if (c3.x != 0.0f) { if (myc < PRIV) priv[myc][lane] = (unsigned short)(b3c    ); ++myc; }
                if (c3.y != 0.0f) { if (myc < PRIV) priv[myc][lane] = (unsigned short)(b3c + 1); ++myc; }
                if (c3.z != 0.0f) { if (myc < PRIV) priv[myc][lane] = (unsigned short)(b3c + 2); ++myc; }
                if (c3.w != 0.0f) { if (myc < PRIV) priv[myc][lane] = (unsigned short)(b3c + 3); ++myc; }
                c0 = n0; c1 = n1; c2 = n2; c3 = n3;
            }
            if (myc > PRIV) myc = PRIV;

            int inc = myc;
            #pragma unroll
            for (int o = 1; o < 32; o <<= 1) {
                int t = __shfl_up_sync(0xffffffffu, inc, o);
                if (lane >= o) inc += t;
            }
            int base = inc - myc;
            int cnt  = __shfl_sync(0xffffffffu, inc, 31);
            if (cnt > CAP) cnt = CAP;
            unsigned short* wc = sC + lr * CAP;
            for (int j = 0; j < myc; ++j) {
                int p = base + j;
                if (p < CAP) wc[p] = priv[j][lane];
            }
            __syncwarp();

            const float* lw = LW + (size_t)row * NN;
            float* wv = sV + lr * CAP;
            float s = 0.0f;
            #pragma unroll
            for (int j = 0; j < CAP / 32; ++j) {
                int k = j * 32 + lane;
                if (k < cnt) {
                    unsigned short c = wc[k];
                    float v = __ldcs(&lw[c]);
                    wv[k] = v;
                    s += v;
                }
            }
            #pragma unroll
            for (int o = 16; o; o >>= 1) s += __shfl_xor_sync(0xffffffffu, s, o);
            if (lane == 0) {
                sCnt[lr]  = cnt;
                g_s1[row] = s;
            }
        }
    }
    __syncthreads();

    // ---------------- phase 1b: prep on blocks 0..64 -------------------------
    if (bid < 64) {
        float* scr = (float*)uBuf;
        int d = bid;
        int e = tid & 63, q = tid >> 6;
        float p = 0.0f;
        #pragma unroll
        for (int j = 0; j < 16; ++j) {
            int f = q * 16 + j;
            p += __ldg(&W0[f * DD + d]) * __ldg(&W1[e * DD + f]);
        }
        scr[q * DD + e] = p;
        __syncthreads();
        float pe = 0.0f;
        if (tid < DD) pe = scr[tid] + scr[DD + tid] + scr[2 * DD + tid] + scr[3 * DD + tid];
        __syncthreads();
        if (tid < DD) scr[tid] = pe;
        __syncthreads();
        float m = 0.0f;
        #pragma unroll
        for (int j = 0; j < 16; ++j) {
            int ee = q * 16 + j;
            m += scr[ee] * __ldg(&W2[e * DD + ee]);
        }
        scr[DD + q * DD + e] = m;
        __syncthreads();
        if (tid < DD)
            g_M[d * DD + tid] = scr[DD + tid] + scr[2 * DD + tid] +
                                scr[3 * DD + tid] + scr[4 * DD + tid];
    } else if (bid == 64) {
        float* scr = (float*)uBuf;
        int t = tid & 63, q = tid >> 6;
        float s = 0.0f, s1p = 0.0f;
        #pragma unroll
        for (int j = 0; j < 16; ++j) {
            int f = q * 16 + j;
            s   += __ldg(&W1[t * DD + f]) * __ldg(&b0[f]);
            s1p += __ldg(&W2[t * DD + f]) * __ldg(&b1[f]);
        }
        scr[q * DD + t]       = s;
        scr[256 + q * DD + t] = s1p;
        __syncthreads();
        if (tid < DD) {
            g_c1[tid] = scr[256 + tid] + scr[320 + tid] + scr[384 + tid] + scr[448 + tid];
            scr[512 + tid] = scr[tid] + scr[64 + tid] + scr[128 + tid] + scr[192 + tid];
        }
        __syncthreads();
        float c0p = 0.0f;
        #pragma unroll
        for (int j = 0; j < 16; ++j) {
            int ee = q * 16 + j;
            c0p += __ldg(&W2[t * DD + ee]) * scr[512 + ee];
        }
        __syncthreads();
        scr[q * DD + t] = c0p;
        __syncthreads();
        if (tid < DD) g_c0[tid] = scr[tid] + scr[64 + tid] + scr[128 + tid] + scr[192 + tid];
    }

    // ---------------- layer 1: y1 = w x (fp32 gathers, fp16 store) ----------
    int r = tid >> 4, l = tid & 15;
    bool active = (r < nrows);
    int row = row0 + (active ? r : 0);
    int cnt = active ? sCnt[r] : 0;
    const unsigned short* cr = sC + (active ? r : 0) * CAP;
    const float*          vr = sV + (active ? r : 0) * CAP;

    float4 y = spmm_row_f32(reinterpret_cast<const float4*>(x), cr, vr, cnt, l);
    if (active)
        reinterpret_cast<uint2*>(g_buf0)[(size_t)row * 16 + l] = pack_half4(y);

    grid_barrier();   // buf0 + s1 + M/c0/c1 complete chip-wide

    // stage M into uBuf
    {
        float4* sM4 = reinterpret_cast<float4*>(uBuf);
        const float4* gm4 = reinterpret_cast<const float4*>(g_M);
        #pragma unroll
        for (int j = 0; j < 4; ++j) sM4[j * 256 + tid] = gm4[j * 256 + tid];
    }

    // ---------------- layer 2: y2 = w y1 (pipelined fp16), s2 = w s1 --------
    y = spmm_row_f16(reinterpret_cast<const uint2*>(g_buf0), cr, vr, cnt, l);
    if (active)
        reinterpret_cast<uint2*>(g_buf1)[(size_t)row * 16 + l] = pack_half4(y);

    {
        float s2a = 0.0f;
        for (int kk = l; kk < cnt; kk += 16)
            s2a += vr[kk] * __ldg(&g_s1[cr[kk]]);
        #pragma unroll
        for (int o = 8; o; o >>= 1) s2a += __shfl_xor_sync(0xffffffffu, s2a, o);
        if (active && l == 0) g_s2[row] = s2a;
    }

    grid_barrier();   // buf1 + s2 complete chip-wide

    // ---------------- layer 3: out = (w y2) M + s2 c0^T + s1 c1^T + b2 ------
    y = spmm_row_f16(reinterpret_cast<const uint2*>(g_buf1), cr, vr, cnt, l);
    if (active)
        reinterpret_cast<float4*>(&shY[r][0])[l] = y;
    __syncthreads();

    if (active) {
        const float* sM = (const float*)uBuf;
        float s1v = g_s1[row], s2v = g_s2[row];
        float4 c0v = __ldg(&reinterpret_cast<const float4*>(g_c0)[l]);
        float4 c1v = __ldg(&reinterpret_cast<const float4*>(g_c1)[l]);
        float4 bv  = __ldg(&reinterpret_cast<const float4*>(b2)[l]);

        float4 acc;
        acc.x = s2v * c0v.x + s1v * c1v.x + bv.x;
        acc.y = s2v * c0v.y + s1v * c1v.y + bv.y;
        acc.z = s2v * c0v.z + s1v * c1v.z + bv.z;
        acc.w = s2v * c0v.w + s1v * c1v.w + bv.w;

        #pragma unroll 8
        for (int d = 0; d < DD; ++d) {
            float yd  = shY[r][d];
            float4 m4 = reinterpret_cast<const float4*>(sM + d * DD)[l];
            acc.x += yd * m4.x; acc.y += yd * m4.y;
            acc.z += yd * m4.z; acc.w += yd * m4.w;
        }
        reinterpret_cast<float4*>(out)[(size_t)row * 16 + l] = acc;
    }
}

// ============================================================================
// Launch (1 kernel)
// ============================================================================
extern "C" void kernel_launch(void* const* d_in, const int* in_sizes, int n_in,
                              void* d_out, int out_size) {
    const float* x  = (const float*)d_in[0];
    const float* A  = (const float*)d_in[1];
    const float* LW = (const float*)d_in[2];
    const float* W0 = (const float*)d_in[3];
    const float* b0 = (const float*)d_in[4];
    const float* W1 = (const float*)d_in[5];
    const float* b1 = (const float*)d_in[6];
    const float* W2 = (const float*)d_in[7];
    const float* b2 = (const float*)d_in[8];

    mega_kernel<<<GRID, 256>>>(A, LW, x, W0, b0, W1, b1, W2, b2, (float*)d_out);
}